// round 9
// baseline (speedup 1.0000x reference)
#include <cuda_runtime.h>
#include <math.h>

#define NB   1024
#define NR   2336
#define NK   2
// Cin = 4, Cout = 16 (fixed)

__device__ float g_cls[NB * NK];

// ---------------------------------------------------------------------------
// Fused kernel: projection + routing. One CTA per (b,k); u_ji computed from
// u and W (L2-resident) straight into smem quad-planes. No global scratch.
// ---------------------------------------------------------------------------
// smem layout (floats):
//   4 quad-planes of PSTRIDE float4 each: plane[q][r] = u_ji[r][4q..4q+3]
//   PSTRIDE = 2338 float4 => plane-to-plane offset = 9352 words = 8 (mod 32)
//   banks: store pattern (lanes = 2 routes x 4 quads per 8-lane phase) and
//   load pattern (lanes = 8 consecutive routes, fixed quad) both conflict-free.
#define PSTRIDE  2338
#define OFF_BS   (4 * PSTRIDE * 4)          // 37408 : logits b[r], NR floats
#define OFF_RED  (OFF_BS + NR)              // 39744 : 32 x float4 partials
#define OFF_ZRED (OFF_RED + 128)            // 39872 : 8 floats
#define OFF_V    (OFF_ZRED + 8)             // 39880 : 4 x float4 (v vector)
#define OFF_CLS  (OFF_V + 16)               // 39896 : 1 float
#define SMEM_FLOATS (OFF_CLS + 4)
#define SMEM_BYTES  (SMEM_FLOATS * 4)       // 159600 B -> 1 CTA/SM

__device__ __forceinline__ void squash_store(const float4* red, float4* v4s,
                                             float* clsp, float cn)
{
    float s[16];
#pragma unroll
    for (int qq = 0; qq < 4; qq++) {
        float4 a = red[qq];
        s[qq*4+0] = a.x * cn; s[qq*4+1] = a.y * cn;
        s[qq*4+2] = a.z * cn; s[qq*4+3] = a.w * cn;
    }
    float n = 0.f;
#pragma unroll
    for (int o = 0; o < 16; o++) n += s[o] * s[o];
    // squash: v = (n/(1+n)) * s / sqrt(n);  |v| = n/(1+n)
    float f = n / ((1.f + n) * sqrtf(fmaxf(n, 1e-30f)));
#pragma unroll
    for (int qq = 0; qq < 4; qq++)
        v4s[qq] = make_float4(f*s[qq*4+0], f*s[qq*4+1], f*s[qq*4+2], f*s[qq*4+3]);
    *clsp = n / (1.f + n);
}

#define XOR_RED4(a, off) do { \
    a.x += __shfl_xor_sync(0xffffffffu, a.x, off); \
    a.y += __shfl_xor_sync(0xffffffffu, a.y, off); \
    a.z += __shfl_xor_sync(0xffffffffu, a.z, off); \
    a.w += __shfl_xor_sync(0xffffffffu, a.w, off); } while (0)

// Phase-1 body: thread (g = route-in-chunk, q = out-quad) computes one quad.
#define PROJ_BODY(r) do { \
    float4 uu = __ldg(&ub[(r)]); \
    const float4* wp = Wb + (size_t)(r) * 16 + q; \
    float4 w0 = __ldg(wp);      float4 w1 = __ldg(wp + 4); \
    float4 w2 = __ldg(wp + 8);  float4 w3 = __ldg(wp + 12); \
    float4 o; \
    o.x = fmaf(uu.x,w0.x, fmaf(uu.y,w1.x, fmaf(uu.z,w2.x, uu.w*w3.x))); \
    o.y = fmaf(uu.x,w0.y, fmaf(uu.y,w1.y, fmaf(uu.z,w2.y, uu.w*w3.y))); \
    o.z = fmaf(uu.x,w0.z, fmaf(uu.y,w1.z, fmaf(uu.z,w2.z, uu.w*w3.z))); \
    o.w = fmaf(uu.x,w0.w, fmaf(uu.y,w1.w, fmaf(uu.z,w2.w, uu.w*w3.w))); \
    acc.x += o.x; acc.y += o.y; acc.z += o.z; acc.w += o.w; \
    plane[q * PSTRIDE + (r)] = o; } while (0)

__global__ void __launch_bounds__(256, 1) caps_fused_kernel(
    const float4* __restrict__ u4,   // u as float4: [b*NR + r]
    const float4* __restrict__ W4)   // W as float4: [(k*NR+r)*16 + i*4 + oq]
{
    extern __shared__ float sm[];
    float4* plane = (float4*)sm;
    float*  bs    = sm + OFF_BS;
    float4* red   = (float4*)(sm + OFF_RED);
    float*  zred  = sm + OFF_ZRED;
    float4* v4s   = (float4*)(sm + OFF_V);

    const int t = threadIdx.x;
    const int lane = t & 31, warp = t >> 5;
    const int bid = blockIdx.x;              // = b*2 + k
    const int b = bid >> 1, k = bid & 1;

    const float4* ub = u4 + (size_t)b * NR;
    const float4* Wb = W4 + (size_t)k * NR * 16;

    // --- Phase 1: projection into quad-planes, fused sweep-1 (uniform c) ---
    const int q = t & 3;                     // out-quad
    const int g = t >> 2;                    // route-in-chunk 0..63
    float4 acc = make_float4(0.f, 0.f, 0.f, 0.f);
#pragma unroll 2
    for (int c = 0; c < 36; c++) {
        int r = c * 64 + g;
        PROJ_BODY(r);
    }
    {   // tail chunk: 2336 = 36*64 + 32 -> only g < 32 valid
        int r = 36 * 64 + g;
        if (r < NR) PROJ_BODY(r);
    }

    // reduce acc across threads sharing q
    XOR_RED4(acc, 4); XOR_RED4(acc, 8); XOR_RED4(acc, 16);
    if (lane < 4) red[warp * 4 + lane] = acc;
    __syncthreads();
    if (warp == 0) {
        float4 a = red[lane];
        XOR_RED4(a, 4); XOR_RED4(a, 8); XOR_RED4(a, 16);
        if (lane < 4) red[lane] = a;
    }
    __syncthreads();
    if (t == 0) squash_store(red, v4s, sm + OFF_CLS, 1.f / (float)NR);
    __syncthreads();

    // --- Phase 2: two fused (b-update + softmax s-sweep) iterations ---
    // Thread-per-route: full 16-dot in registers, no inner-loop shuffles.
#pragma unroll
    for (int it = 0; it < 2; it++) {
        const float4 v0 = v4s[0], v1 = v4s[1], v2 = v4s[2], v3 = v4s[3];
        float4 a0 = make_float4(0,0,0,0), a1 = a0, a2 = a0, a3 = a0;
        float Z = 0.f;
        for (int r = t; r < NR; r += 256) {
            float4 x0 = plane[0*PSTRIDE + r];
            float4 x1 = plane[1*PSTRIDE + r];
            float4 x2 = plane[2*PSTRIDE + r];
            float4 x3 = plane[3*PSTRIDE + r];
            float d = x0.x*v0.x;
            d = fmaf(x0.y, v0.y, d); d = fmaf(x0.z, v0.z, d); d = fmaf(x0.w, v0.w, d);
            d = fmaf(x1.x, v1.x, d); d = fmaf(x1.y, v1.y, d);
            d = fmaf(x1.z, v1.z, d); d = fmaf(x1.w, v1.w, d);
            d = fmaf(x2.x, v2.x, d); d = fmaf(x2.y, v2.y, d);
            d = fmaf(x2.z, v2.z, d); d = fmaf(x2.w, v2.w, d);
            d = fmaf(x3.x, v3.x, d); d = fmaf(x3.y, v3.y, d);
            d = fmaf(x3.z, v3.z, d); d = fmaf(x3.w, v3.w, d);
            float bn;
            if (it == 0) { bn = d; bs[r] = bn; }
            else         { bn = bs[r] + d; }
            float e = __expf(bn);            // logits bounded, no max-shift
            Z += e;
            a0.x = fmaf(e, x0.x, a0.x); a0.y = fmaf(e, x0.y, a0.y);
            a0.z = fmaf(e, x0.z, a0.z); a0.w = fmaf(e, x0.w, a0.w);
            a1.x = fmaf(e, x1.x, a1.x); a1.y = fmaf(e, x1.y, a1.y);
            a1.z = fmaf(e, x1.z, a1.z); a1.w = fmaf(e, x1.w, a1.w);
            a2.x = fmaf(e, x2.x, a2.x); a2.y = fmaf(e, x2.y, a2.y);
            a2.z = fmaf(e, x2.z, a2.z); a2.w = fmaf(e, x2.w, a2.w);
            a3.x = fmaf(e, x3.x, a3.x); a3.y = fmaf(e, x3.y, a3.y);
            a3.z = fmaf(e, x3.z, a3.z); a3.w = fmaf(e, x3.w, a3.w);
        }
        // intra-warp reduce (each thread holds full 16-vec + Z)
        XOR_RED4(a0, 1); XOR_RED4(a0, 2); XOR_RED4(a0, 4); XOR_RED4(a0, 8); XOR_RED4(a0, 16);
        XOR_RED4(a1, 1); XOR_RED4(a1, 2); XOR_RED4(a1, 4); XOR_RED4(a1, 8); XOR_RED4(a1, 16);
        XOR_RED4(a2, 1); XOR_RED4(a2, 2); XOR_RED4(a2, 4); XOR_RED4(a2, 8); XOR_RED4(a2, 16);
        XOR_RED4(a3, 1); XOR_RED4(a3, 2); XOR_RED4(a3, 4); XOR_RED4(a3, 8); XOR_RED4(a3, 16);
        Z += __shfl_xor_sync(0xffffffffu, Z, 1);
        Z += __shfl_xor_sync(0xffffffffu, Z, 2);
        Z += __shfl_xor_sync(0xffffffffu, Z, 4);
        Z += __shfl_xor_sync(0xffffffffu, Z, 8);
        Z += __shfl_xor_sync(0xffffffffu, Z, 16);
        if (lane == 0) {
            red[warp*4+0] = a0; red[warp*4+1] = a1;
            red[warp*4+2] = a2; red[warp*4+3] = a3;
            zred[warp] = Z;
        }
        __syncthreads();
        if (warp == 0) {
            int w = lane & 7;                 // all 32 lanes converged
            float4 c0 = red[w*4+0], c1 = red[w*4+1], c2 = red[w*4+2], c3 = red[w*4+3];
            float Zt = zred[w];
            XOR_RED4(c0, 1); XOR_RED4(c0, 2); XOR_RED4(c0, 4);
            XOR_RED4(c1, 1); XOR_RED4(c1, 2); XOR_RED4(c1, 4);
            XOR_RED4(c2, 1); XOR_RED4(c2, 2); XOR_RED4(c2, 4);
            XOR_RED4(c3, 1); XOR_RED4(c3, 2); XOR_RED4(c3, 4);
            Zt += __shfl_xor_sync(0xffffffffu, Zt, 1);
            Zt += __shfl_xor_sync(0xffffffffu, Zt, 2);
            Zt += __shfl_xor_sync(0xffffffffu, Zt, 4);
            if (lane == 0) {
                float4 rr[4] = {c0, c1, c2, c3};
                squash_store(rr, v4s, sm + OFF_CLS, 1.f / Zt);
            }
        }
        __syncthreads();
    }

    if (t == 0) g_cls[bid] = sm[OFF_CLS];
}

// ---------------------------------------------------------------------------
// Final softmax over K=2 classes per batch
// ---------------------------------------------------------------------------
__global__ void caps_softmax_kernel(float* __restrict__ out)
{
    int b = blockIdx.x * blockDim.x + threadIdx.x;
    if (b < NB) {
        float c0 = g_cls[2*b], c1 = g_cls[2*b + 1];
        float m  = fmaxf(c0, c1);
        float e0 = expf(c0 - m), e1 = expf(c1 - m);
        float inv = 1.f / (e0 + e1);
        out[2*b]     = e0 * inv;
        out[2*b + 1] = e1 * inv;
    }
}

// ---------------------------------------------------------------------------
extern "C" void kernel_launch(void* const* d_in, const int* in_sizes, int n_in,
                              void* d_out, int out_size)
{
    const float4* u4 = (const float4*)d_in[0];   // u: [1024,2336,4] f32
    const float4* W4 = (const float4*)d_in[1];   // W: [2,2336,4,16] f32
    (void)in_sizes; (void)n_in; (void)out_size;

    cudaFuncSetAttribute(caps_fused_kernel,
                         cudaFuncAttributeMaxDynamicSharedMemorySize, SMEM_BYTES);

    caps_fused_kernel<<<NB * NK, 256, SMEM_BYTES>>>(u4, W4);
    caps_softmax_kernel<<<(NB + 255) / 256, 256>>>((float*)d_out);
}

// round 10
// speedup vs baseline: 1.5989x; 1.5989x over previous
#include <cuda_runtime.h>
#include <cuda_fp16.h>
#include <math.h>

#define NB   1024
#define NR   2336
#define NK   2
// Cin = 4, Cout = 16 (fixed)

__device__ float g_cls[NB * NK];

// ---------------------------------------------------------------------------
// Fused kernel: projection + routing, TWO batches per CTA (same k).
// u_ji tiles live in smem as fp16 half-planes:
//   per batch: planeA (quads 0-1, 16 B/route) | 64 B pad | planeB (quads 2-3)
//   A->B offset = 37440 B == 64 (mod 128)  => STS.64 stores (4 routes x 4 quads
//   per 16-lane phase cover exactly 128 contiguous-bank bytes) and per-route
//   LDS.128 loads (8 consecutive routes x 16 B) are both conflict-free.
// ---------------------------------------------------------------------------
#define PB_OFF      37440                   // planeB offset inside a tile
#define TILE_BYTES  74816                   // 2*37376 + 64 pad
#define P0_OFF      0
#define P1_OFF      TILE_BYTES              // 74816
#define BS0_OFF     (2*TILE_BYTES)          // 149632 : logits b[r], batch 0
#define BS1_OFF     (BS0_OFF + NR*4)        // 158976 : logits, batch 1
#define RED0_OFF    (BS1_OFF + NR*4)        // 168320 : 64 float4
#define RED1_OFF    (RED0_OFF + 1024)       // 169344
#define ZRED0_OFF   (RED1_OFF + 1024)       // 170368 : 16 floats
#define ZRED1_OFF   (ZRED0_OFF + 64)
#define V0_OFF      (ZRED1_OFF + 64)        // 170496 : 4 float4
#define V1_OFF      (V0_OFF + 64)
#define CLS0_OFF    (V1_OFF + 64)           // 170624
#define CLS1_OFF    (CLS0_OFF + 4)
#define SMEM_BYTES  (CLS1_OFF + 12)         // ~170.6 KB -> 1 CTA/SM

__device__ __forceinline__ void squash_store(const float4* red, float4* v4s,
                                             float* clsp, float cn)
{
    float s[16];
#pragma unroll
    for (int qq = 0; qq < 4; qq++) {
        float4 a = red[qq];
        s[qq*4+0] = a.x * cn; s[qq*4+1] = a.y * cn;
        s[qq*4+2] = a.z * cn; s[qq*4+3] = a.w * cn;
    }
    float n = 0.f;
#pragma unroll
    for (int o = 0; o < 16; o++) n += s[o] * s[o];
    // squash: v = (n/(1+n)) * s / sqrt(n);  |v| = n/(1+n)
    float f = n / ((1.f + n) * sqrtf(fmaxf(n, 1e-30f)));
#pragma unroll
    for (int qq = 0; qq < 4; qq++)
        v4s[qq] = make_float4(f*s[qq*4+0], f*s[qq*4+1], f*s[qq*4+2], f*s[qq*4+3]);
    *clsp = n / (1.f + n);
}

#define XOR_RED4(a, off) do { \
    a.x += __shfl_xor_sync(0xffffffffu, a.x, off); \
    a.y += __shfl_xor_sync(0xffffffffu, a.y, off); \
    a.z += __shfl_xor_sync(0xffffffffu, a.z, off); \
    a.w += __shfl_xor_sync(0xffffffffu, a.w, off); } while (0)

// Phase-1 body: thread (g = route-in-chunk, q = out-quad) computes one quad
// for BOTH batches, sharing the 4 W loads.
#define PROJ2(r) do { \
    const float4* wp = Wb + (size_t)(r) * 16 + q; \
    float4 w0 = __ldg(wp);      float4 w1 = __ldg(wp + 4); \
    float4 w2 = __ldg(wp + 8);  float4 w3 = __ldg(wp + 12); \
    float4 uu0 = __ldg(&ub0[(r)]); \
    float4 uu1 = __ldg(&ub1[(r)]); \
    float4 o0, o1; \
    o0.x = fmaf(uu0.x,w0.x, fmaf(uu0.y,w1.x, fmaf(uu0.z,w2.x, uu0.w*w3.x))); \
    o0.y = fmaf(uu0.x,w0.y, fmaf(uu0.y,w1.y, fmaf(uu0.z,w2.y, uu0.w*w3.y))); \
    o0.z = fmaf(uu0.x,w0.z, fmaf(uu0.y,w1.z, fmaf(uu0.z,w2.z, uu0.w*w3.z))); \
    o0.w = fmaf(uu0.x,w0.w, fmaf(uu0.y,w1.w, fmaf(uu0.z,w2.w, uu0.w*w3.w))); \
    o1.x = fmaf(uu1.x,w0.x, fmaf(uu1.y,w1.x, fmaf(uu1.z,w2.x, uu1.w*w3.x))); \
    o1.y = fmaf(uu1.x,w0.y, fmaf(uu1.y,w1.y, fmaf(uu1.z,w2.y, uu1.w*w3.y))); \
    o1.z = fmaf(uu1.x,w0.z, fmaf(uu1.y,w1.z, fmaf(uu1.z,w2.z, uu1.w*w3.z))); \
    o1.w = fmaf(uu1.x,w0.w, fmaf(uu1.y,w1.w, fmaf(uu1.z,w2.w, uu1.w*w3.w))); \
    acc0.x += o0.x; acc0.y += o0.y; acc0.z += o0.z; acc0.w += o0.w; \
    acc1.x += o1.x; acc1.y += o1.y; acc1.z += o1.z; acc1.w += o1.w; \
    __half2 hA0 = __floats2half2_rn(o0.x, o0.y); \
    __half2 hB0 = __floats2half2_rn(o0.z, o0.w); \
    __half2 hA1 = __floats2half2_rn(o1.x, o1.y); \
    __half2 hB1 = __floats2half2_rn(o1.z, o1.w); \
    uint2 hv0, hv1; \
    hv0.x = *reinterpret_cast<unsigned*>(&hA0); \
    hv0.y = *reinterpret_cast<unsigned*>(&hB0); \
    hv1.x = *reinterpret_cast<unsigned*>(&hA1); \
    hv1.y = *reinterpret_cast<unsigned*>(&hB1); \
    dst0[(size_t)(r) * 2] = hv0; \
    dst1[(size_t)(r) * 2] = hv1; } while (0)

#define H2F2(dst, i, hw) do { \
    float2 _f = __half22float2(*reinterpret_cast<const __half2*>(&(hw))); \
    dst[i] = _f.x; dst[(i)+1] = _f.y; } while (0)

__global__ void __launch_bounds__(512, 1) caps_fused_kernel(
    const float4* __restrict__ u4,   // u as float4: [b*NR + r]
    const float4* __restrict__ W4)   // W as float4: [(k*NR+r)*16 + i*4 + oq]
{
    extern __shared__ char smb[];
    const int t = threadIdx.x;
    const int lane = t & 31, warp = t >> 5;
    const int cid = blockIdx.x;
    const int k  = cid & 1;
    const int b0 = (cid >> 1) * 2;           // batches b0, b0+1

    const float4* ub0 = u4 + (size_t)b0 * NR;
    const float4* ub1 = ub0 + NR;
    const float4* Wb  = W4 + (size_t)k * NR * 16;

    float4* red0  = (float4*)(smb + RED0_OFF);
    float4* red1  = (float4*)(smb + RED1_OFF);
    float*  zred0 = (float*)(smb + ZRED0_OFF);
    float*  zred1 = (float*)(smb + ZRED1_OFF);
    float4* v4s0  = (float4*)(smb + V0_OFF);
    float4* v4s1  = (float4*)(smb + V1_OFF);

    // --- Phase 1: projection -> fp16 planes, fused sweep-1 (uniform c) ---
    const int q = t & 3;                     // out-quad
    const int g = t >> 2;                    // route-in-chunk 0..127
    // each thread's store base: half-plane A (q=0,1) or B (q=2,3), slot q&1
    uint2* dst0 = (uint2*)(smb + P0_OFF + (q < 2 ? 0 : PB_OFF)) + (q & 1);
    uint2* dst1 = (uint2*)(smb + P1_OFF + (q < 2 ? 0 : PB_OFF)) + (q & 1);

    float4 acc0 = make_float4(0.f,0.f,0.f,0.f);
    float4 acc1 = make_float4(0.f,0.f,0.f,0.f);
#pragma unroll 2
    for (int c = 0; c < 18; c++) {           // 18*128 = 2304 routes
        int r = c * 128 + g;
        PROJ2(r);
    }
    if (g < 32) {                            // tail: routes 2304..2335
        int r = 2304 + g;
        PROJ2(r);
    }

    // reduce acc across threads sharing q (8 per warp, 16 warps)
    XOR_RED4(acc0, 4); XOR_RED4(acc0, 8); XOR_RED4(acc0, 16);
    XOR_RED4(acc1, 4); XOR_RED4(acc1, 8); XOR_RED4(acc1, 16);
    if (lane < 4) { red0[warp*4 + lane] = acc0; red1[warp*4 + lane] = acc1; }
    __syncthreads();
    if (warp < 2) {
        float4* rg = warp ? red1 : red0;
        float4 a = rg[lane], bx = rg[lane + 32];
        a.x += bx.x; a.y += bx.y; a.z += bx.z; a.w += bx.w;
        XOR_RED4(a, 4); XOR_RED4(a, 8); XOR_RED4(a, 16);
        if (lane < 4) rg[lane] = a;
        __syncwarp();
        if (lane == 0)
            squash_store(rg, warp ? v4s1 : v4s0,
                         (float*)(smb + (warp ? CLS1_OFF : CLS0_OFF)),
                         1.f / (float)NR);
    }
    __syncthreads();

    // --- Phase 2: two fused (b-update + softmax s-sweep) iterations ---
    // warps 0-7 -> batch 0, warps 8-15 -> batch 1; thread-per-route.
    const int grp = warp >> 3;
    const int tt  = t & 255;
    const uint4* pA = (const uint4*)(smb + (grp ? P1_OFF : P0_OFF));
    const uint4* pB = (const uint4*)(smb + (grp ? P1_OFF : P0_OFF) + PB_OFF);
    float* bs     = (float*)(smb + (grp ? BS1_OFF : BS0_OFF));
    float4* redg  = grp ? red1 : red0;
    float*  zredg = grp ? zred1 : zred0;
    float4* v4sg  = grp ? v4s1 : v4s0;

#pragma unroll
    for (int it = 0; it < 2; it++) {
        float vv[16];
        {
            float4 t0 = v4sg[0], t1 = v4sg[1], t2 = v4sg[2], t3 = v4sg[3];
            vv[0]=t0.x; vv[1]=t0.y; vv[2]=t0.z; vv[3]=t0.w;
            vv[4]=t1.x; vv[5]=t1.y; vv[6]=t1.z; vv[7]=t1.w;
            vv[8]=t2.x; vv[9]=t2.y; vv[10]=t2.z; vv[11]=t2.w;
            vv[12]=t3.x; vv[13]=t3.y; vv[14]=t3.z; vv[15]=t3.w;
        }
        float a[16];
#pragma unroll
        for (int o = 0; o < 16; o++) a[o] = 0.f;
        float Z = 0.f;

#pragma unroll 2
        for (int r = tt; r < NR; r += 256) {
            uint4 ha = pA[r];                // quads 0-1 (8 halfs)
            uint4 hb = pB[r];                // quads 2-3
            float x[16];
            H2F2(x, 0,  ha.x); H2F2(x, 2,  ha.y);
            H2F2(x, 4,  ha.z); H2F2(x, 6,  ha.w);
            H2F2(x, 8,  hb.x); H2F2(x, 10, hb.y);
            H2F2(x, 12, hb.z); H2F2(x, 14, hb.w);
            float d = x[0] * vv[0];
#pragma unroll
            for (int o = 1; o < 16; o++) d = fmaf(x[o], vv[o], d);
            float bn;
            if (it == 0) { bn = d; bs[r] = d; }
            else         { bn = bs[r] + d; }
            float e = __expf(bn);            // logits bounded, no max-shift
            Z += e;
#pragma unroll
            for (int o = 0; o < 16; o++) a[o] = fmaf(e, x[o], a[o]);
        }

        // intra-warp reduce
#pragma unroll
        for (int off = 1; off < 32; off <<= 1) {
#pragma unroll
            for (int o = 0; o < 16; o++)
                a[o] += __shfl_xor_sync(0xffffffffu, a[o], off);
            Z += __shfl_xor_sync(0xffffffffu, Z, off);
        }
        if (lane == 0) {
            int w = warp & 7;
            redg[w*4+0] = make_float4(a[0],  a[1],  a[2],  a[3]);
            redg[w*4+1] = make_float4(a[4],  a[5],  a[6],  a[7]);
            redg[w*4+2] = make_float4(a[8],  a[9],  a[10], a[11]);
            redg[w*4+3] = make_float4(a[12], a[13], a[14], a[15]);
            zredg[w] = Z;
        }
        __syncthreads();
        if (warp < 2) {                      // warp0 -> batch0, warp1 -> batch1
            float4* rg = warp ? red1 : red0;
            float*  zg = warp ? zred1 : zred0;
            float4 c4 = rg[lane];            // 32 entries: (w 0..7) x (q 0..3)
            XOR_RED4(c4, 4); XOR_RED4(c4, 8); XOR_RED4(c4, 16);
            float Zt = (lane < 8) ? zg[lane] : 0.f;
            Zt += __shfl_xor_sync(0xffffffffu, Zt, 1);
            Zt += __shfl_xor_sync(0xffffffffu, Zt, 2);
            Zt += __shfl_xor_sync(0xffffffffu, Zt, 4);
            if (lane < 4) rg[lane] = c4;
            __syncwarp();
            if (lane == 0)
                squash_store(rg, warp ? v4s1 : v4s0,
                             (float*)(smb + (warp ? CLS1_OFF : CLS0_OFF)),
                             1.f / Zt);
        }
        __syncthreads();
    }

    if (t == 0) {
        g_cls[(size_t)b0 * 2 + k]       = *(float*)(smb + CLS0_OFF);
        g_cls[(size_t)(b0 + 1) * 2 + k] = *(float*)(smb + CLS1_OFF);
    }
}

// ---------------------------------------------------------------------------
// Final softmax over K=2 classes per batch
// ---------------------------------------------------------------------------
__global__ void caps_softmax_kernel(float* __restrict__ out)
{
    int b = blockIdx.x * blockDim.x + threadIdx.x;
    if (b < NB) {
        float c0 = g_cls[2*b], c1 = g_cls[2*b + 1];
        float m  = fmaxf(c0, c1);
        float e0 = expf(c0 - m), e1 = expf(c1 - m);
        float inv = 1.f / (e0 + e1);
        out[2*b]     = e0 * inv;
        out[2*b + 1] = e1 * inv;
    }
}

// ---------------------------------------------------------------------------
extern "C" void kernel_launch(void* const* d_in, const int* in_sizes, int n_in,
                              void* d_out, int out_size)
{
    const float4* u4 = (const float4*)d_in[0];   // u: [1024,2336,4] f32
    const float4* W4 = (const float4*)d_in[1];   // W: [2,2336,4,16] f32
    (void)in_sizes; (void)n_in; (void)out_size;

    cudaFuncSetAttribute(caps_fused_kernel,
                         cudaFuncAttributeMaxDynamicSharedMemorySize, SMEM_BYTES);

    caps_fused_kernel<<<NB, 512, SMEM_BYTES>>>(u4, W4);
    caps_softmax_kernel<<<(NB + 255) / 256, 256>>>((float*)d_out);
}